// round 3
// baseline (speedup 1.0000x reference)
#include <cuda_runtime.h>
#include <cstddef>

#define EPSF 1e-6f
#define LAMBDAF 0.01f

// Problem constants (fixed shapes)
//  x: (4,16,16,16,16)  a: (4,16,16,16,1)  w: (144,32,4,4)
//  out: p_out (4,14,14,32,16) ++ a_out (4,14,14,32,1)
#define NCAP 144
#define CCAP 32
#define NPOS 784           // 4*14*14
#define POUT_ELEMS 401408  // 784*32*16

__device__ __forceinline__ float warp_max(float v) {
#pragma unroll
    for (int o = 16; o; o >>= 1) v = fmaxf(v, __shfl_xor_sync(0xffffffffu, v, o));
    return v;
}
__device__ __forceinline__ float warp_sum(float v) {
#pragma unroll
    for (int o = 16; o; o >>= 1) v += __shfl_xor_sync(0xffffffffu, v, o);
    return v;
}

struct Smem {
    float pose[2304];   // [n*16 + p], pose patch
    float a[144];       // a_in per n
    float WS[8 * 548];  // per-warp reduction staging (stride-17 padded); WS[0..544) reused as halflog buf
    float S1[544];      // sum r*v   [c*17+p]
    float S2[544];      // sum r*v^2 [c*17+p]
    float MU[544];      // mu        [c*17+p]
    float I2S[544];     // 1/(2 sigma^2)
    float RSB[8 * 33];  // per-warp rsum staging
    float RS[32];       // r_sum per c
    float Lc[32];       // log(a_out+eps) - sum_p 0.5 log sigma^2
    float AO[32];       // a_out per c
};

// One pass over n: recompute votes v[n,c,:]; optionally do the E-step
// (responsibilities via warp softmax over c=lane) and accumulate the next
// M-step sums S1 = sum_n r_n v, S2 = sum_n r_n v^2, RS = sum_n r_n.
// For HASE=false, r_n = a_n / C (iteration-0 uniform responsibilities).
template <bool HASE>
__device__ __forceinline__ void vote_pass(Smem& sm, const float* __restrict__ w,
                                          int lane, int g, int tid) {
    float mu[16], i2s[16], Lr = 0.f;
    if (HASE) {
#pragma unroll
        for (int p = 0; p < 16; p++) {
            mu[p] = sm.MU[lane * 17 + p];
            i2s[p] = sm.I2S[lane * 17 + p];
        }
        Lr = sm.Lc[lane];
    }
    float T1[16], T2[16];
#pragma unroll
    for (int p = 0; p < 16; p++) { T1[p] = 0.f; T2[p] = 0.f; }
    float rsum = 0.f;

    for (int n = g; n < NCAP; n += 8) {
        // weight[n][c=lane][j][k] : 16 floats, coalesced float4 loads (L2-resident)
        const float4* wp = reinterpret_cast<const float4*>(w + (size_t)((n << 5) + lane) * 16);
        float4 w0 = __ldg(wp + 0), w1 = __ldg(wp + 1), w2 = __ldg(wp + 2), w3 = __ldg(wp + 3);
        const float* ps = sm.pose + n * 16;  // smem broadcast (all lanes same n)
        float v[16];
#pragma unroll
        for (int i = 0; i < 4; i++) {
            float p0 = ps[4 * i + 0], p1 = ps[4 * i + 1], p2 = ps[4 * i + 2], p3 = ps[4 * i + 3];
            v[4 * i + 0] = fmaf(p0, w0.x, fmaf(p1, w1.x, fmaf(p2, w2.x, p3 * w3.x)));
            v[4 * i + 1] = fmaf(p0, w0.y, fmaf(p1, w1.y, fmaf(p2, w2.y, p3 * w3.y)));
            v[4 * i + 2] = fmaf(p0, w0.z, fmaf(p1, w1.z, fmaf(p2, w2.z, p3 * w3.z)));
            v[4 * i + 3] = fmaf(p0, w0.w, fmaf(p1, w1.w, fmaf(p2, w2.w, p3 * w3.w)));
        }
        float rn;
        if (HASE) {
            // ln_ap[n,c] = -sum_p (v-mu)^2/(2 sig^2) + [log(a_out+eps) - sum_p 0.5 log sig^2]
            // (constant -8*ln(2pi) dropped: softmax-invariant)
            float ds = 0.f;
#pragma unroll
            for (int p = 0; p < 16; p++) {
                float t = v[p] - mu[p];
                ds = fmaf(t * i2s[p], t, ds);
            }
            float ln = Lr - ds;
            float m = warp_max(ln);          // softmax over c == over lanes
            float e = __expf(ln - m);
            float se = warp_sum(e);
            rn = sm.a[n] * e / se;           // r = softmax_c * a_in
        } else {
            rn = sm.a[n] * (1.0f / 32.0f);   // r0 = a_in / C
        }
        rsum += rn;
#pragma unroll
        for (int p = 0; p < 16; p++) {
            float rv = rn * v[p];
            T1[p] += rv;
            T2[p] = fmaf(rv, v[p], T2[p]);
        }
    }

    // ---- cross-warp reduction (deterministic, conflict-free stride-17) ----
#pragma unroll
    for (int p = 0; p < 16; p++) sm.WS[g * 548 + lane * 17 + p] = T1[p];
    sm.RSB[g * 33 + lane] = rsum;
    __syncthreads();
    for (int q = tid; q < 512; q += 256) {
        int c = q >> 4, p = q & 15;
        float s = 0.f;
#pragma unroll
        for (int gg = 0; gg < 8; gg++) s += sm.WS[gg * 548 + c * 17 + p];
        sm.S1[c * 17 + p] = s;
    }
    if (tid < 32) {
        float s = 0.f;
#pragma unroll
        for (int gg = 0; gg < 8; gg++) s += sm.RSB[gg * 33 + tid];
        sm.RS[tid] = s;
    }
    __syncthreads();
#pragma unroll
    for (int p = 0; p < 16; p++) sm.WS[g * 548 + lane * 17 + p] = T2[p];
    __syncthreads();
    for (int q = tid; q < 512; q += 256) {
        int c = q >> 4, p = q & 15;
        float s = 0.f;
#pragma unroll
        for (int gg = 0; gg < 8; gg++) s += sm.WS[gg * 548 + c * 17 + p];
        sm.S2[c * 17 + p] = s;
    }
    __syncthreads();
}

// M-step statistics: mu, sigma^2 (via E[v^2]-mu^2 with the exact coeff
// normalization coeff = r/(rsum+eps)), a_out, and the per-c softmax constant Lc.
__device__ __forceinline__ void stats(Smem& sm, const float* __restrict__ bu,
                                      const float* __restrict__ ba, int tid) {
    for (int q = tid; q < 512; q += 256) {
        int c = q >> 4, p = q & 15, qi = c * 17 + p;
        float rs = sm.RS[c];
        float inv = 1.0f / (rs + EPSF);
        float mu = sm.S1[qi] * inv;
        // sigma^2 = S2/(rs+eps) - mu^2 * (2 - rs/(rs+eps)) + eps
        float sig = fmaf(-mu * mu, 2.0f - rs * inv, sm.S2[qi] * inv) + EPSF;
        sm.MU[qi] = mu;
        sm.I2S[qi] = 0.5f / sig;
        sm.WS[qi] = 0.5f * __logf(sig);  // halflog buffer (WS reuse)
    }
    __syncthreads();
    if (tid < 32) {
        int c = tid;
        float sumh = 0.f;
#pragma unroll
        for (int p = 0; p < 16; p++) sumh += sm.WS[c * 17 + p];
        float cost = (16.0f * bu[c] + sumh) * sm.RS[c];  // sum_p (beta_u + 0.5 log sig^2) * r_sum
        float logit = LAMBDAF * (ba[c] - cost);
        float ao = 1.0f / (1.0f + __expf(-logit));
        sm.AO[c] = ao;
        sm.Lc[c] = __logf(ao + EPSF) - sumh;
    }
    __syncthreads();
}

__global__ __launch_bounds__(256, 2) void convcaps_kernel(
    const float* __restrict__ x, const float* __restrict__ a,
    const float* __restrict__ w, const float* __restrict__ bu,
    const float* __restrict__ ba, const int* __restrict__ itp,
    float* __restrict__ out) {
    __shared__ Smem sm;
    int tid = threadIdx.x, lane = tid & 31, g = tid >> 5;
    int pid = blockIdx.x;
    int b = pid / 196;
    int rem = pid - b * 196;
    int oy = rem / 14;
    int ox = rem - oy * 14;

    // Patch gather: n = (ki*3+kj)*16 + bc ; pose_s[n*16+p] = x[b, oy+ki, ox+kj, bc, p]
    for (int q = tid; q < 2304; q += 256) {
        int n = q >> 4, p = q & 15;
        int bc = n & 15, kk = n >> 4;
        int ki = kk / 3, kj = kk - ki * 3;
        sm.pose[q] =
            x[(((size_t)(b * 16 + oy + ki) * 16 + (ox + kj)) * 16 + bc) * 16 + p];
    }
    for (int n = tid; n < NCAP; n += 256) {
        int bc = n & 15, kk = n >> 4;
        int ki = kk / 3, kj = kk - ki * 3;
        sm.a[n] = a[((size_t)(b * 16 + oy + ki) * 16 + (ox + kj)) * 16 + bc];
    }
    __syncthreads();

    int iters = 2;
    if (itp) {
        int iv = __ldg(itp);
        if (iv >= 1 && iv <= 64) {
            iters = iv;
        } else {
            float f = __int_as_float(iv);  // guard against float-encoded scalar
            if (f >= 1.0f && f <= 64.0f) iters = (int)f;
        }
    }

    // iteration 0: uniform responsibilities
    vote_pass<false>(sm, w, lane, g, tid);
    stats(sm, bu, ba, tid);
    // iterations 1..iters-1: fused E-step (of prev iter) + M-accumulation
    for (int it = 1; it < iters; ++it) {
        vote_pass<true>(sm, w, lane, g, tid);
        stats(sm, bu, ba, tid);
    }

    // outputs: p_out (pid*512 + c*16+p) then a_out (POUT_ELEMS + pid*32 + c)
    float* pout = out + (size_t)pid * 512;
    for (int q = tid; q < 512; q += 256) {
        int c = q >> 4, p = q & 15;
        pout[q] = sm.MU[c * 17 + p];
    }
    if (tid < 32) out[POUT_ELEMS + pid * 32 + tid] = sm.AO[tid];
}

extern "C" void kernel_launch(void* const* d_in, const int* in_sizes, int n_in,
                              void* d_out, int out_size) {
    const float* x = (const float*)d_in[0];
    const float* a = (const float*)d_in[1];
    const float* w = (const float*)d_in[2];
    const float* bu = (const float*)d_in[3];
    const float* ba = (const float*)d_in[4];
    const int* itp = (n_in >= 6) ? (const int*)d_in[5] : nullptr;
    convcaps_kernel<<<NPOS, 256>>>(x, a, w, bu, ba, itp, (float*)d_out);
}

// round 4
// speedup vs baseline: 1.2784x; 1.2784x over previous
#include <cuda_runtime.h>
#include <cuda_fp16.h>
#include <cstddef>

#define EPSF 1e-6f
#define LAMBDAF 0.01f

// Problem constants (fixed shapes)
//  x: (4,16,16,16,16)  a: (4,16,16,16,1)  w: (144,32,4,4)
//  out: p_out (4,14,14,32,16) ++ a_out (4,14,14,32,1)
#define NCAP 144
#define CCAP 32
#define NPOS 784           // 4*14*14
#define POUT_ELEMS 401408  // 784*32*16
#define WHALF_ELEMS (NCAP * CCAP * 16)  // 73728 halves = 144KB (L1-resident)

// fp16 weight staging buffer, layout [n][k2][c][8]:
//   wh[((n*2+k2)*32 + c)*8 + j] = w[n][c][ k2*8 + j ]   (j,k flattened: m = jrow*4+k)
// so uint4 #0 holds w[j=0][k0..3], w[j=1][k0..3]; uint4 #1 holds j=2,3.
__device__ __half g_wh[WHALF_ELEMS];

__global__ void convert_w_kernel(const float* __restrict__ w) {
    int q = blockIdx.x * 256 + threadIdx.x;  // 0..73727
    if (q >= WHALF_ELEMS) return;
    int j = q & 7;
    int c = (q >> 3) & 31;
    int k2 = (q >> 8) & 1;
    int n = q >> 9;
    g_wh[q] = __float2half_rn(w[((n * 32 + c) << 4) + k2 * 8 + j]);
}

__device__ __forceinline__ float warp_max(float v) {
#pragma unroll
    for (int o = 16; o; o >>= 1) v = fmaxf(v, __shfl_xor_sync(0xffffffffu, v, o));
    return v;
}
__device__ __forceinline__ float warp_sum(float v) {
#pragma unroll
    for (int o = 16; o; o >>= 1) v += __shfl_xor_sync(0xffffffffu, v, o);
    return v;
}

struct Smem {
    float pose[2304];   // [n*16 + p], pose patch
    float a[144];       // a_in per n
    float WS[8 * 548];  // per-warp reduction staging (stride-17 padded); [0..544) reused as halflog buf
    float S1[544];      // sum r*v   [c*17+p]
    float S2[544];      // sum r*v^2 [c*17+p]
    float MU[544];      // mu        [c*17+p]
    float I2S[544];     // 1/(2 sigma^2)
    float RSB[8 * 33];  // per-warp rsum staging
    float RS[32];       // r_sum per c
    float Lc[32];       // log(a_out+eps) - sum_p 0.5 log sigma^2
    float AO[32];       // a_out per c
};

// One pass over n: recompute votes v[n,c,:] from fp16 weights; optionally the
// E-step (warp softmax over c=lane) fused with the next M-step accumulation.
template <bool HASE>
__device__ __forceinline__ void vote_pass(Smem& sm, int lane, int g, int tid) {
    float mu[16], i2s[16], Lr = 0.f;
    if (HASE) {
#pragma unroll
        for (int p = 0; p < 16; p++) {
            mu[p] = sm.MU[lane * 17 + p];
            i2s[p] = sm.I2S[lane * 17 + p];
        }
        Lr = sm.Lc[lane];
    }
    float T1[16], T2[16];
#pragma unroll
    for (int p = 0; p < 16; p++) { T1[p] = 0.f; T2[p] = 0.f; }
    float rsum = 0.f;

    const uint4* whv = reinterpret_cast<const uint4*>(g_wh);  // 1 uint4 = 8 halves

#pragma unroll 2
    for (int n = g; n < NCAP; n += 8) {
        // weight loads: 2×LDG.128 per thread; warp-contiguous 512B each (L1-resident)
        uint4 ua = __ldg(whv + (n * 2 + 0) * 32 + lane);  // rows j=0,1
        uint4 ub = __ldg(whv + (n * 2 + 1) * 32 + lane);  // rows j=2,3
        const __half2* ha = reinterpret_cast<const __half2*>(&ua);
        const __half2* hb = reinterpret_cast<const __half2*>(&ub);
        float w0[4], w1[4], w2[4], w3[4];
        {
            float2 t;
            t = __half22float2(ha[0]); w0[0] = t.x; w0[1] = t.y;
            t = __half22float2(ha[1]); w0[2] = t.x; w0[3] = t.y;
            t = __half22float2(ha[2]); w1[0] = t.x; w1[1] = t.y;
            t = __half22float2(ha[3]); w1[2] = t.x; w1[3] = t.y;
            t = __half22float2(hb[0]); w2[0] = t.x; w2[1] = t.y;
            t = __half22float2(hb[1]); w2[2] = t.x; w2[3] = t.y;
            t = __half22float2(hb[2]); w3[0] = t.x; w3[1] = t.y;
            t = __half22float2(hb[3]); w3[2] = t.x; w3[3] = t.y;
        }
        const float* ps = sm.pose + n * 16;  // smem broadcast (all lanes same n)
        float v[16];
#pragma unroll
        for (int i = 0; i < 4; i++) {
            float p0 = ps[4 * i + 0], p1 = ps[4 * i + 1], p2 = ps[4 * i + 2], p3 = ps[4 * i + 3];
#pragma unroll
            for (int k = 0; k < 4; k++)
                v[4 * i + k] = fmaf(p0, w0[k], fmaf(p1, w1[k], fmaf(p2, w2[k], p3 * w3[k])));
        }
        float rn;
        if (HASE) {
            // ln_ap[n,c] = -sum_p (v-mu)^2/(2 sig^2) + [log(a_out+eps) - sum_p 0.5 log sig^2]
            float ds = 0.f;
#pragma unroll
            for (int p = 0; p < 16; p++) {
                float t = v[p] - mu[p];
                ds = fmaf(t * i2s[p], t, ds);
            }
            float ln = Lr - ds;
            float m = warp_max(ln);  // softmax over c == over lanes
            float e = __expf(ln - m);
            float se = warp_sum(e);
            rn = sm.a[n] * __fdividef(e, se);  // r = softmax_c * a_in
        } else {
            rn = sm.a[n] * (1.0f / 32.0f);  // iter-0: r0 = a_in / C
        }
        rsum += rn;
#pragma unroll
        for (int p = 0; p < 16; p++) {
            float rv = rn * v[p];
            T1[p] += rv;
            T2[p] = fmaf(rv, v[p], T2[p]);
        }
    }

    // ---- cross-warp reduction (deterministic, conflict-free stride-17) ----
#pragma unroll
    for (int p = 0; p < 16; p++) sm.WS[g * 548 + lane * 17 + p] = T1[p];
    sm.RSB[g * 33 + lane] = rsum;
    __syncthreads();
    for (int q = tid; q < 512; q += 256) {
        int c = q >> 4, p = q & 15;
        float s = 0.f;
#pragma unroll
        for (int gg = 0; gg < 8; gg++) s += sm.WS[gg * 548 + c * 17 + p];
        sm.S1[c * 17 + p] = s;
    }
    if (tid < 32) {
        float s = 0.f;
#pragma unroll
        for (int gg = 0; gg < 8; gg++) s += sm.RSB[gg * 33 + tid];
        sm.RS[tid] = s;
    }
    __syncthreads();
#pragma unroll
    for (int p = 0; p < 16; p++) sm.WS[g * 548 + lane * 17 + p] = T2[p];
    __syncthreads();
    for (int q = tid; q < 512; q += 256) {
        int c = q >> 4, p = q & 15;
        float s = 0.f;
#pragma unroll
        for (int gg = 0; gg < 8; gg++) s += sm.WS[gg * 548 + c * 17 + p];
        sm.S2[c * 17 + p] = s;
    }
    __syncthreads();
}

// M-step statistics: mu, sigma^2 (E[v^2]-mu^2 with exact coeff normalization),
// a_out, and the per-c softmax constant Lc.
__device__ __forceinline__ void stats(Smem& sm, const float* __restrict__ bu,
                                      const float* __restrict__ ba, int tid) {
    for (int q = tid; q < 512; q += 256) {
        int c = q >> 4, p = q & 15, qi = c * 17 + p;
        float rs = sm.RS[c];
        float inv = __fdividef(1.0f, rs + EPSF);
        float mu = sm.S1[qi] * inv;
        // sigma^2 = S2/(rs+eps) - mu^2 * (2 - rs/(rs+eps)) + eps
        float sig = fmaf(-mu * mu, 2.0f - rs * inv, sm.S2[qi] * inv) + EPSF;
        sm.MU[qi] = mu;
        sm.I2S[qi] = __fdividef(0.5f, sig);
        sm.WS[qi] = 0.5f * __logf(sig);  // halflog buffer (WS reuse)
    }
    __syncthreads();
    if (tid < 32) {
        int c = tid;
        float sumh = 0.f;
#pragma unroll
        for (int p = 0; p < 16; p++) sumh += sm.WS[c * 17 + p];
        float cost = (16.0f * bu[c] + sumh) * sm.RS[c];
        float logit = LAMBDAF * (ba[c] - cost);
        float ao = __fdividef(1.0f, 1.0f + __expf(-logit));
        sm.AO[c] = ao;
        sm.Lc[c] = __logf(ao + EPSF) - sumh;
    }
    __syncthreads();
}

__global__ __launch_bounds__(256, 2) void convcaps_kernel(
    const float* __restrict__ x, const float* __restrict__ a,
    const float* __restrict__ bu, const float* __restrict__ ba,
    const int* __restrict__ itp, float* __restrict__ out) {
    __shared__ Smem sm;
    int tid = threadIdx.x, lane = tid & 31, g = tid >> 5;
    int pid = blockIdx.x;
    int b = pid / 196;
    int rem = pid - b * 196;
    int oy = rem / 14;
    int ox = rem - oy * 14;

    // Patch gather: n = (ki*3+kj)*16 + bc ; pose[n*16+p] = x[b, oy+ki, ox+kj, bc, p]
    for (int q = tid; q < 2304; q += 256) {
        int n = q >> 4, p = q & 15;
        int bc = n & 15, kk = n >> 4;
        int ki = kk / 3, kj = kk - ki * 3;
        sm.pose[q] = x[(((size_t)(b * 16 + oy + ki) * 16 + (ox + kj)) * 16 + bc) * 16 + p];
    }
    for (int n = tid; n < NCAP; n += 256) {
        int bc = n & 15, kk = n >> 4;
        int ki = kk / 3, kj = kk - ki * 3;
        sm.a[n] = a[((size_t)(b * 16 + oy + ki) * 16 + (ox + kj)) * 16 + bc];
    }
    __syncthreads();

    int iters = 2;
    if (itp) {
        int iv = __ldg(itp);
        if (iv >= 1 && iv <= 64) {
            iters = iv;
        } else {
            float f = __int_as_float(iv);  // guard against float-encoded scalar
            if (f >= 1.0f && f <= 64.0f) iters = (int)f;
        }
    }

    // iteration 0: uniform responsibilities
    vote_pass<false>(sm, lane, g, tid);
    stats(sm, bu, ba, tid);
    // iterations 1..iters-1: fused E-step (of prev iter) + M-accumulation
    for (int it = 1; it < iters; ++it) {
        vote_pass<true>(sm, lane, g, tid);
        stats(sm, bu, ba, tid);
    }

    // outputs: p_out (pid*512 + c*16+p) then a_out (POUT_ELEMS + pid*32 + c)
    float* pout = out + (size_t)pid * 512;
    for (int q = tid; q < 512; q += 256) {
        int c = q >> 4, p = q & 15;
        pout[q] = sm.MU[c * 17 + p];
    }
    if (tid < 32) out[POUT_ELEMS + pid * 32 + tid] = sm.AO[tid];
}

extern "C" void kernel_launch(void* const* d_in, const int* in_sizes, int n_in,
                              void* d_out, int out_size) {
    const float* x = (const float*)d_in[0];
    const float* a = (const float*)d_in[1];
    const float* w = (const float*)d_in[2];
    const float* bu = (const float*)d_in[3];
    const float* ba = (const float*)d_in[4];
    const int* itp = (n_in >= 6) ? (const int*)d_in[5] : nullptr;
    convert_w_kernel<<<(WHALF_ELEMS + 255) / 256, 256>>>(w);
    convcaps_kernel<<<NPOS, 256>>>(x, a, bu, ba, itp, (float*)d_out);
}

// round 5
// speedup vs baseline: 1.3612x; 1.0647x over previous
#include <cuda_runtime.h>
#include <cuda_fp16.h>
#include <cstddef>

#define EPSF 1e-6f
#define LAMBDAF 0.01f

// Problem constants (fixed shapes)
//  x: (4,16,16,16,16)  a: (4,16,16,16,1)  w: (144,32,4,4)
//  out: p_out (4,14,14,32,16) ++ a_out (4,14,14,32,1)
#define NCAP 144
#define CCAP 32
#define NPOS 784           // 4*14*14
#define POUT_ELEMS 401408  // 784*32*16
#define WHALF_ELEMS (NCAP * CCAP * 16)  // 73728 halves = 144KB (L1-resident)

// fp16 weight staging buffer, layout [n][k2][c][8]:
//   wh[((n*2+k2)*32 + c)*8 + j] = w[n][c][ k2*8 + j ]
__device__ __half g_wh[WHALF_ELEMS];

// One thread produces one uint4 (8 halves) from two float4 loads.
__global__ void convert_w_kernel(const float* __restrict__ w) {
    int q = blockIdx.x * 256 + threadIdx.x;  // 0..9215
    if (q >= WHALF_ELEMS / 8) return;
    int c = q & 31;
    int k2 = (q >> 5) & 1;
    int n = q >> 6;
    const float4* src = reinterpret_cast<const float4*>(w + ((n * 32 + c) << 4) + k2 * 8);
    float4 f0 = __ldg(src + 0), f1 = __ldg(src + 1);
    __half2 h[4];
    h[0] = __floats2half2_rn(f0.x, f0.y);
    h[1] = __floats2half2_rn(f0.z, f0.w);
    h[2] = __floats2half2_rn(f1.x, f1.y);
    h[3] = __floats2half2_rn(f1.z, f1.w);
    reinterpret_cast<uint4*>(g_wh)[q] = *reinterpret_cast<uint4*>(h);
}

__device__ __forceinline__ float warp_max(float v) {
#pragma unroll
    for (int o = 16; o; o >>= 1) v = fmaxf(v, __shfl_xor_sync(0xffffffffu, v, o));
    return v;
}
__device__ __forceinline__ float warp_sum(float v) {
#pragma unroll
    for (int o = 16; o; o >>= 1) v += __shfl_xor_sync(0xffffffffu, v, o);
    return v;
}

struct Smem {
    float pose[2304];   // [n*16 + p], pose patch
    float a[144];       // a_in per n
    float WS[8 * 548];  // per-warp reduction staging (stride-17 padded); [0..544) reused as halflog buf
    float S1[544];      // sum r*v   [c*17+p]
    float S2[544];      // sum r*v^2 [c*17+p]
    float MU[544];      // mu        [c*17+p]
    float I2S[544];     // 1/(2 sigma^2)
    float RSB[8 * 33];  // per-warp rsum staging
    float RS[32];       // r_sum per c
    float Lc[32];       // log(a_out+eps) - sum_p 0.5 log sigma^2
    float AO[32];       // a_out per c
};

// One pass over n: recompute votes v[n,c,:] from fp16 weights; optionally the
// E-step (warp softmax over c=lane) fused with the next M-step accumulation.
// E-step uses the pass-constant shift M0 = max_c(Lr') (valid since ds >= 0),
// removing the per-n warp_max chain; ds is computed as (A*v+B)*v with the
// constant term folded into Lr'.
template <bool HASE>
__device__ __forceinline__ void vote_pass(Smem& sm, int lane, int g, int tid) {
    float A[16], Bv[16], Lr2 = 0.f, M0 = 0.f;
    if (HASE) {
        float C = 0.f;
#pragma unroll
        for (int p = 0; p < 16; p++) {
            float m_ = sm.MU[lane * 17 + p];
            float ii = sm.I2S[lane * 17 + p];
            A[p] = ii;
            Bv[p] = -2.0f * ii * m_;
            C = fmaf(ii * m_, m_, C);
        }
        Lr2 = sm.Lc[lane] - C;
        M0 = warp_max(Lr2);  // upper bound of ln over lanes: safe softmax shift
    }
    float T1[16], T2[16];
#pragma unroll
    for (int p = 0; p < 16; p++) { T1[p] = 0.f; T2[p] = 0.f; }
    float rsum = 0.f;

    const uint4* whv = reinterpret_cast<const uint4*>(g_wh);  // 1 uint4 = 8 halves

#pragma unroll 2
    for (int n = g; n < NCAP; n += 8) {
        // weight loads: 2×LDG.128 per thread; warp-contiguous 512B each (L1-resident)
        uint4 ua = __ldg(whv + (n * 2 + 0) * 32 + lane);  // rows j=0,1
        uint4 ub = __ldg(whv + (n * 2 + 1) * 32 + lane);  // rows j=2,3
        const __half2* ha = reinterpret_cast<const __half2*>(&ua);
        const __half2* hb = reinterpret_cast<const __half2*>(&ub);
        float w0[4], w1[4], w2[4], w3[4];
        {
            float2 t;
            t = __half22float2(ha[0]); w0[0] = t.x; w0[1] = t.y;
            t = __half22float2(ha[1]); w0[2] = t.x; w0[3] = t.y;
            t = __half22float2(ha[2]); w1[0] = t.x; w1[1] = t.y;
            t = __half22float2(ha[3]); w1[2] = t.x; w1[3] = t.y;
            t = __half22float2(hb[0]); w2[0] = t.x; w2[1] = t.y;
            t = __half22float2(hb[1]); w2[2] = t.x; w2[3] = t.y;
            t = __half22float2(hb[2]); w3[0] = t.x; w3[1] = t.y;
            t = __half22float2(hb[3]); w3[2] = t.x; w3[3] = t.y;
        }
        const float* ps = sm.pose + n * 16;  // smem broadcast (all lanes same n)
        float v[16];
#pragma unroll
        for (int i = 0; i < 4; i++) {
            float p0 = ps[4 * i + 0], p1 = ps[4 * i + 1], p2 = ps[4 * i + 2], p3 = ps[4 * i + 3];
#pragma unroll
            for (int k = 0; k < 4; k++)
                v[4 * i + k] = fmaf(p0, w0[k], fmaf(p1, w1[k], fmaf(p2, w2[k], p3 * w3[k])));
        }
        float rn;
        if (HASE) {
            // ln = Lr' - sum_p (A_p v_p + B_p) v_p
            float ds = 0.f;
#pragma unroll
            for (int p = 0; p < 16; p++) {
                float t = fmaf(A[p], v[p], Bv[p]);
                ds = fmaf(t, v[p], ds);
            }
            float ln = Lr2 - ds;
            float e = __expf(ln - M0);
            float se = warp_sum(e);
            if (se < 1e-37f) {  // warp-uniform rescue: exact max (never in practice)
                float m = warp_max(ln);
                e = __expf(ln - m);
                se = warp_sum(e);
            }
            rn = sm.a[n] * __fdividef(e, se);  // r = softmax_c * a_in
        } else {
            rn = sm.a[n] * (1.0f / 32.0f);  // iter-0: r0 = a_in / C
        }
        rsum += rn;
#pragma unroll
        for (int p = 0; p < 16; p++) {
            float rv = rn * v[p];
            T1[p] += rv;
            T2[p] = fmaf(rv, v[p], T2[p]);
        }
    }

    // ---- cross-warp reduction (deterministic, conflict-free stride-17) ----
#pragma unroll
    for (int p = 0; p < 16; p++) sm.WS[g * 548 + lane * 17 + p] = T1[p];
    sm.RSB[g * 33 + lane] = rsum;
    __syncthreads();
    for (int q = tid; q < 512; q += 256) {
        int c = q >> 4, p = q & 15;
        float s = 0.f;
#pragma unroll
        for (int gg = 0; gg < 8; gg++) s += sm.WS[gg * 548 + c * 17 + p];
        sm.S1[c * 17 + p] = s;
    }
    if (tid < 32) {
        float s = 0.f;
#pragma unroll
        for (int gg = 0; gg < 8; gg++) s += sm.RSB[gg * 33 + tid];
        sm.RS[tid] = s;
    }
    __syncthreads();
#pragma unroll
    for (int p = 0; p < 16; p++) sm.WS[g * 548 + lane * 17 + p] = T2[p];
    __syncthreads();
    for (int q = tid; q < 512; q += 256) {
        int c = q >> 4, p = q & 15;
        float s = 0.f;
#pragma unroll
        for (int gg = 0; gg < 8; gg++) s += sm.WS[gg * 548 + c * 17 + p];
        sm.S2[c * 17 + p] = s;
    }
    __syncthreads();
}

// M-step statistics: mu, sigma^2 (E[v^2]-mu^2 with exact coeff normalization),
// a_out, and the per-c softmax constant Lc.
__device__ __forceinline__ void stats(Smem& sm, const float* __restrict__ bu,
                                      const float* __restrict__ ba, int tid) {
    for (int q = tid; q < 512; q += 256) {
        int c = q >> 4, p = q & 15, qi = c * 17 + p;
        float rs = sm.RS[c];
        float inv = __fdividef(1.0f, rs + EPSF);
        float mu = sm.S1[qi] * inv;
        // sigma^2 = S2/(rs+eps) - mu^2 * (2 - rs/(rs+eps)) + eps
        float sig = fmaf(-mu * mu, 2.0f - rs * inv, sm.S2[qi] * inv) + EPSF;
        sm.MU[qi] = mu;
        sm.I2S[qi] = __fdividef(0.5f, sig);
        sm.WS[qi] = 0.5f * __logf(sig);  // halflog buffer (WS reuse)
    }
    __syncthreads();
    if (tid < 32) {
        int c = tid;
        float sumh = 0.f;
#pragma unroll
        for (int p = 0; p < 16; p++) sumh += sm.WS[c * 17 + p];
        float cost = (16.0f * bu[c] + sumh) * sm.RS[c];
        float logit = LAMBDAF * (ba[c] - cost);
        float ao = __fdividef(1.0f, 1.0f + __expf(-logit));
        sm.AO[c] = ao;
        sm.Lc[c] = __logf(ao + EPSF) - sumh;
    }
    __syncthreads();
}

__global__ __launch_bounds__(256, 2) void convcaps_kernel(
    const float* __restrict__ x, const float* __restrict__ a,
    const float* __restrict__ bu, const float* __restrict__ ba,
    const int* __restrict__ itp, float* __restrict__ out) {
    __shared__ Smem sm;
    int tid = threadIdx.x, lane = tid & 31, g = tid >> 5;
    int pid = blockIdx.x;
    int b = pid / 196;
    int rem = pid - b * 196;
    int oy = rem / 14;
    int ox = rem - oy * 14;

    // Patch gather (float4-vectorized): n = (ki*3+kj)*16 + bc
    for (int q = tid; q < 576; q += 256) {
        int n = q >> 2, f = q & 3;
        int bc = n & 15, kk = n >> 4;
        int ki = kk / 3, kj = kk - ki * 3;
        const float4* src = reinterpret_cast<const float4*>(
            x + (((size_t)(b * 16 + oy + ki) * 16 + (ox + kj)) * 16 + bc) * 16);
        reinterpret_cast<float4*>(sm.pose)[q] = __ldg(src + f);
    }
    for (int n = tid; n < NCAP; n += 256) {
        int bc = n & 15, kk = n >> 4;
        int ki = kk / 3, kj = kk - ki * 3;
        sm.a[n] = a[((size_t)(b * 16 + oy + ki) * 16 + (ox + kj)) * 16 + bc];
    }
    __syncthreads();

    int iters = 2;
    if (itp) {
        int iv = __ldg(itp);
        if (iv >= 1 && iv <= 64) {
            iters = iv;
        } else {
            float f = __int_as_float(iv);  // guard against float-encoded scalar
            if (f >= 1.0f && f <= 64.0f) iters = (int)f;
        }
    }

    // iteration 0: uniform responsibilities
    vote_pass<false>(sm, lane, g, tid);
    stats(sm, bu, ba, tid);
    // iterations 1..iters-1: fused E-step (of prev iter) + M-accumulation
    for (int it = 1; it < iters; ++it) {
        vote_pass<true>(sm, lane, g, tid);
        stats(sm, bu, ba, tid);
    }

    // outputs: p_out (pid*512 + c*16+p) then a_out (POUT_ELEMS + pid*32 + c)
    float* pout = out + (size_t)pid * 512;
    for (int q = tid; q < 512; q += 256) {
        int c = q >> 4, p = q & 15;
        pout[q] = sm.MU[c * 17 + p];
    }
    if (tid < 32) out[POUT_ELEMS + pid * 32 + tid] = sm.AO[tid];
}

extern "C" void kernel_launch(void* const* d_in, const int* in_sizes, int n_in,
                              void* d_out, int out_size) {
    const float* x = (const float*)d_in[0];
    const float* a = (const float*)d_in[1];
    const float* w = (const float*)d_in[2];
    const float* bu = (const float*)d_in[3];
    const float* ba = (const float*)d_in[4];
    const int* itp = (n_in >= 6) ? (const int*)d_in[5] : nullptr;
    convert_w_kernel<<<(WHALF_ELEMS / 8 + 255) / 256, 256>>>(w);
    convcaps_kernel<<<NPOS, 256>>>(x, a, bu, ba, itp, (float*)d_out);
}